// round 2
// baseline (speedup 1.0000x reference)
#include <cuda_runtime.h>
#include <cstdint>

// Problem constants
constexpr int B_   = 8;
constexpr int H_   = 8;
constexpr int LQ_  = 1024;
constexpr int LM_  = 4096;
constexpr int DM_  = 512;
constexpr int DK_  = 64;
constexpr int TOPK_ = 32;

// Attention kernel tiling
constexpr int QT   = 8;     // queries per block
constexpr int CK   = 256;   // key chunk cached in smem
constexpr int KROW = 68;    // padded K row (floats) -> conflict-free float4 LDS

// Scratch (static device arrays: allocation-free)
__device__ float g_q[B_*H_*LQ_*DK_];   // 16 MB  [B,H,LQ,Dk]
__device__ float g_k[B_*H_*LM_*DK_];   // 64 MB  [B,H,LM,Dk]
__device__ float g_v[B_*H_*LM_*DK_];   // 64 MB  [B,H,LM,Dk]
__device__ float g_x[B_*LQ_*DM_];      // 16 MB  [B,LQ,DM] pre-output-proj

// ---------------- shared memory layout for attention kernel ----------------
constexpr int OFF_QS   = 0;                    // QT*DK floats
constexpr int OFF_KS   = OFF_QS + QT*DK_;      // CK*KROW floats
constexpr int OFF_SC   = OFF_KS + CK*KROW;     // QT*LM floats
constexpr int OFF_HIST = OFF_SC + QT*LM_;      // 256 uints
constexpr int OFF_SELS = OFF_HIST + 256;       // 32 floats
constexpr int OFF_SELI = OFF_SELS + 32;        // 32 ints
constexpr int OFF_PV   = OFF_SELI + 32;        // 32 floats
constexpr int OFF_PART = OFF_PV + 32;          // 256 floats
constexpr int OFF_MISC = OFF_PART + 256;       // 8 uints
constexpr int SMEM_FLOATS = OFF_MISC + 8;
constexpr int SMEM_BYTES  = SMEM_FLOATS * 4;   // ~205 KB

// order-preserving float -> uint
__device__ __forceinline__ unsigned ordu(float x) {
    unsigned u = __float_as_uint(x);
    return (u & 0x80000000u) ? ~u : (u | 0x80000000u);
}

// Warp-parallel radix bin search: find largest bin B s.t. suffix(B) >= kneed.
// Returns B and above = suffix(B+1) (count strictly above bin B). t<32 lanes.
__device__ __forceinline__ void radix_step(const unsigned* hist, unsigned kneed,
                                           int lane, int& binOut, unsigned& aboveOut)
{
    unsigned s = 0;
    #pragma unroll
    for (int j = 0; j < 8; j++) s += hist[lane*8 + j];
    unsigned suf = s;
    #pragma unroll
    for (int off = 1; off < 32; off <<= 1) {
        unsigned v = __shfl_down_sync(0xffffffffu, suf, off);
        if (lane + off < 32) suf += v;
    }
    unsigned sufN = __shfl_down_sync(0xffffffffu, suf, 1);
    if (lane == 31) sufN = 0;
    unsigned m = __ballot_sync(0xffffffffu, (suf >= kneed) && (sufN < kneed));
    int g = __ffs(m) - 1;
    unsigned base = __shfl_sync(0xffffffffu, sufN, g);

    unsigned hv = (lane < 8) ? hist[g*8 + lane] : 0u;
    unsigned suf2 = hv;
    #pragma unroll
    for (int off = 1; off < 8; off <<= 1) {
        unsigned v = __shfl_down_sync(0xffffffffu, suf2, off);
        if (lane + off < 8) suf2 += v;
    }
    suf2 += base;
    unsigned suf2N = __shfl_down_sync(0xffffffffu, suf2, 1);
    if (lane == 7) suf2N = base;
    unsigned m2 = __ballot_sync(0xffffffffu, (lane < 8) && (suf2 >= kneed) && (suf2N < kneed));
    int j = __ffs(m2) - 1;
    binOut = g*8 + j;
    aboveOut = __shfl_sync(0xffffffffu, suf2N, j);
}

// ---------------------------------------------------------------------------
// SGEMM: C = A[M,512] @ W[512,512]^T + bias   (torch Linear semantics)
// Two-level accumulation: each 8-wide k-tile accumulates into cacc, folded
// into acc once per tile (cuts sequential-512 rounding noise ~3x).
// head_major: write C as [B, H, L, Dk]; else [M,512].
// grid: (M/128, 4), block: 256 threads, 8x8 per thread.
// ---------------------------------------------------------------------------
__global__ void __launch_bounds__(256, 1)
gemm512_kernel(const float* __restrict__ A, const float* __restrict__ W,
               const float* __restrict__ bias, float* __restrict__ C,
               int L, int head_major)
{
    __shared__ float As[8][128];
    __shared__ float Bs[8][128];

    const int t  = threadIdx.x;
    const int tx = t & 15;
    const int ty = t >> 4;
    const int m0 = blockIdx.x * 128;
    const int n0 = blockIdx.y * 128;
    const int lr = t >> 1;
    const int lc = (t & 1) << 2;

    const float* Ap = A + (size_t)(m0 + lr) * DM_ + lc;
    const float* Wp = W + (size_t)(n0 + lr) * DM_ + lc;

    float acc[8][8];
    #pragma unroll
    for (int i = 0; i < 8; i++)
        #pragma unroll
        for (int j = 0; j < 8; j++) acc[i][j] = 0.f;

    for (int k0 = 0; k0 < DM_; k0 += 8) {
        float4 av = *(const float4*)(Ap + k0);
        float4 wv = *(const float4*)(Wp + k0);
        __syncthreads();
        As[lc+0][lr] = av.x; As[lc+1][lr] = av.y; As[lc+2][lr] = av.z; As[lc+3][lr] = av.w;
        Bs[lc+0][lr] = wv.x; Bs[lc+1][lr] = wv.y; Bs[lc+2][lr] = wv.z; Bs[lc+3][lr] = wv.w;
        __syncthreads();

        float cacc[8][8];
        #pragma unroll
        for (int k = 0; k < 8; k++) {
            float a[8], bb[8];
            #pragma unroll
            for (int i = 0; i < 8; i++) a[i]  = As[k][ty*8 + i];
            #pragma unroll
            for (int j = 0; j < 8; j++) bb[j] = Bs[k][tx*8 + j];
            if (k == 0) {
                #pragma unroll
                for (int i = 0; i < 8; i++)
                    #pragma unroll
                    for (int j = 0; j < 8; j++)
                        cacc[i][j] = a[i] * bb[j];
            } else {
                #pragma unroll
                for (int i = 0; i < 8; i++)
                    #pragma unroll
                    for (int j = 0; j < 8; j++)
                        cacc[i][j] = fmaf(a[i], bb[j], cacc[i][j]);
            }
        }
        #pragma unroll
        for (int i = 0; i < 8; i++)
            #pragma unroll
            for (int j = 0; j < 8; j++)
                acc[i][j] += cacc[i][j];
    }

    #pragma unroll
    for (int i = 0; i < 8; i++) {
        int m  = m0 + ty*8 + i;
        int bb_ = m / L;
        int l   = m - bb_ * L;
        #pragma unroll
        for (int j = 0; j < 8; j++) {
            int n = n0 + tx*8 + j;
            float v = acc[i][j] + bias[n];
            if (head_major) {
                int hh = n >> 6, dk = n & 63;
                C[((size_t)(bb_*H_ + hh) * L + l) * DK_ + dk] = v;
            } else {
                C[(size_t)m * DM_ + n] = v;
            }
        }
    }
}

// ---------------------------------------------------------------------------
// Fused scores + top-32 (EXACT: full 32-bit, 4-pass radix select) + softmax
// + V gather. One block per (b, h, 8-query tile). 256 threads.
// ---------------------------------------------------------------------------
__global__ void __launch_bounds__(256, 1)
attn_topk_kernel(const float* __restrict__ gq, const float* __restrict__ gk,
                 const float* __restrict__ gv, float* __restrict__ gx)
{
    extern __shared__ float sm[];
    float*    qs    = sm + OFF_QS;
    float*    ks    = sm + OFF_KS;
    float*    sc    = sm + OFF_SC;
    unsigned* hist  = (unsigned*)(sm + OFF_HIST);
    float*    sel_s = sm + OFF_SELS;
    int*      sel_i = (int*)(sm + OFF_SELI);
    float*    pvw   = sm + OFF_PV;
    float*    part  = sm + OFF_PART;
    unsigned* misc  = (unsigned*)(sm + OFF_MISC);

    const int t   = threadIdx.x;
    const int qt0 = blockIdx.x * QT;
    const int h   = blockIdx.y;
    const int b   = blockIdx.z;

    // load Q tile (8x64 fp32)
    const float* qbase = gq + ((size_t)(b*H_ + h) * LQ_ + qt0) * DK_;
    if (t < QT*DK_/4) ((float4*)qs)[t] = ((const float4*)qbase)[t];
    __syncthreads();

    // ---- scores: stream K in 256-key chunks, each thread owns one key ----
    const float* kbase = gk + (size_t)(b*H_ + h) * LM_ * DK_;
    for (int c0 = 0; c0 < LM_; c0 += CK) {
        for (int i = t; i < CK*(DK_/4); i += 256) {
            int row = i >> 4, col = i & 15;
            float4 v4 = ((const float4*)(kbase + (size_t)(c0 + row) * DK_))[col];
            *(float4*)(ks + row*KROW + col*4) = v4;
        }
        __syncthreads();

        float acc[QT];
        #pragma unroll
        for (int qi = 0; qi < QT; qi++) acc[qi] = 0.f;
        const float4* krow = (const float4*)(ks + t*KROW);
        #pragma unroll
        for (int d4 = 0; d4 < DK_/4; d4++) {
            float4 kv = krow[d4];
            #pragma unroll
            for (int qi = 0; qi < QT; qi++) {
                float4 qv = ((const float4*)(qs + qi*DK_))[d4];
                acc[qi] += kv.x*qv.x + kv.y*qv.y + kv.z*qv.z + kv.w*qv.w;
            }
        }
        #pragma unroll
        for (int qi = 0; qi < QT; qi++)
            sc[qi*LM_ + c0 + t] = acc[qi] * 0.125f;   // 1/sqrt(64)
        __syncthreads();
    }

    // ---- per query row: exact top-32, softmax, weighted V gather ----
    const float* vbase = gv + (size_t)(b*H_ + h) * LM_ * DK_;
    for (int r = 0; r < QT; r++) {
        const float* row = sc + r*LM_;

        // full 32-bit radix select: 4 passes of 8 bits
        unsigned prefix = 0;
        unsigned kneed  = TOPK_;
        #pragma unroll
        for (int p = 0; p < 4; p++) {
            hist[t] = 0;
            __syncthreads();
            const int shift = 24 - p*8;
            for (int i = t; i < LM_; i += 256) {
                unsigned u = ordu(row[i]);
                if (p == 0 || (u >> (shift + 8)) == prefix)
                    atomicAdd(&hist[(u >> shift) & 255u], 1u);
            }
            __syncthreads();
            if (t < 32) {
                int Bv; unsigned above;
                radix_step(hist, kneed, t, Bv, above);
                if (t == 0) { misc[0] = (unsigned)Bv; misc[1] = above; }
            }
            __syncthreads();
            prefix = (prefix << 8) | misc[0];
            kneed -= misc[1];
            __syncthreads();
        }
        // prefix = EXACT 32-bit ordu threshold; (32-kneed) strictly above;
        // kneed taken from elements exactly equal to the threshold.

        if (t == 0) { misc[2] = 0; misc[3] = 0; }
        __syncthreads();
        const unsigned nAbove = TOPK_ - kneed;
        for (int i = t; i < LM_; i += 256) {
            float v = row[i];
            unsigned u = ordu(v);
            if (u > prefix) {
                unsigned pos = atomicAdd(&misc[2], 1u);
                sel_s[pos] = v; sel_i[pos] = i;
            } else if (u == prefix) {
                unsigned e = atomicAdd(&misc[3], 1u);
                if (e < kneed) { sel_s[nAbove + e] = v; sel_i[nAbove + e] = i; }
            }
        }
        __syncthreads();

        // softmax over the 32 selected scores (warp 0)
        if (t < 32) {
            float v = sel_s[t];
            float mx = v;
            #pragma unroll
            for (int off = 16; off; off >>= 1)
                mx = fmaxf(mx, __shfl_xor_sync(0xffffffffu, mx, off));
            float e = __expf(v - mx);
            float s = e;
            #pragma unroll
            for (int off = 16; off; off >>= 1)
                s += __shfl_xor_sync(0xffffffffu, s, off);
            pvw[t] = e / s;
        }
        __syncthreads();

        // weighted gather of 32 V rows; 4 groups x 64 dims
        {
            int g = t >> 6, d = t & 63;
            float a = 0.f;
            for (int it = g; it < TOPK_; it += 4)
                a += pvw[it] * vbase[(size_t)sel_i[it] * DK_ + d];
            part[t] = a;
        }
        __syncthreads();
        if (t < DK_) {
            float o = part[t] + part[64 + t] + part[128 + t] + part[192 + t];
            gx[((size_t)b * LQ_ + (qt0 + r)) * DM_ + h*DK_ + t] = o;
        }
        __syncthreads();
    }
}

// ---------------------------------------------------------------------------
extern "C" void kernel_launch(void* const* d_in, const int* in_sizes, int n_in,
                              void* d_out, int out_size)
{
    const float* query = (const float*)d_in[0];
    const float* key   = (const float*)d_in[1];
    const float* value = (const float*)d_in[2];
    const float* Wq    = (const float*)d_in[3];
    const float* bq    = (const float*)d_in[4];
    const float* Wk    = (const float*)d_in[5];
    const float* bk    = (const float*)d_in[6];
    const float* Wv    = (const float*)d_in[7];
    const float* bv    = (const float*)d_in[8];
    const float* Wo    = (const float*)d_in[9];
    const float* bo    = (const float*)d_in[10];
    float* out = (float*)d_out;

    float *pq, *pk, *pv, *px;
    cudaGetSymbolAddress((void**)&pq, g_q);
    cudaGetSymbolAddress((void**)&pk, g_k);
    cudaGetSymbolAddress((void**)&pv, g_v);
    cudaGetSymbolAddress((void**)&px, g_x);

    cudaFuncSetAttribute(attn_topk_kernel,
                         cudaFuncAttributeMaxDynamicSharedMemorySize, SMEM_BYTES);

    // projections into head-major scratch
    gemm512_kernel<<<dim3(B_*LQ_/128, DM_/128), 256>>>(query, Wq, bq, pq, LQ_, 1);
    gemm512_kernel<<<dim3(B_*LM_/128, DM_/128), 256>>>(key,   Wk, bk, pk, LM_, 1);
    gemm512_kernel<<<dim3(B_*LM_/128, DM_/128), 256>>>(value, Wv, bv, pv, LM_, 1);

    // fused scores + topk + softmax + gather
    attn_topk_kernel<<<dim3(LQ_/QT, H_, B_), 256, SMEM_BYTES>>>(pq, pk, pv, px);

    // output projection (plain row-major)
    gemm512_kernel<<<dim3(B_*LQ_/128, DM_/128), 256>>>(px, Wo, bo, out, LQ_, 0);
}